// round 1
// baseline (speedup 1.0000x reference)
#include <cuda_runtime.h>

// Problem constants (fixed by the reference).
#define BB 320   // batch
#define CC 80    // label dim
#define DD 128   // feature dim
#define NUM_ANCHORS 30

// Scratch (no allocations allowed -> __device__ globals).
__device__ float g_ns[BB];          // ||source_i||
__device__ float g_nt[BB];          // ||target_i||
__device__ float g_sn[BB];          // sqrt(label_i . label_i)
__device__ unsigned int g_lp[BB * 3]; // packed binary labels (80 bits -> 3 words)
__device__ float g_fd[BB * BB];     // cosine-distance matrix
__device__ unsigned char g_mask[BB * BB]; // 1 = pos (ld<=gamma, p!=a), 2 = neg (ld>=beta)
__device__ float g_div[BB];         // diversity = mean_b fd[a,b]
__device__ float g_partial[BB];     // per-anchor triplet loss sum
__device__ int   g_cnt[BB];         // per-anchor triplet count
__device__ int   g_done;            // last-block ticket

template <int NT>
__device__ __forceinline__ float block_reduce_f(float v, float* sh) {
    int t = threadIdx.x;
    sh[t] = v;
    __syncthreads();
#pragma unroll
    for (int s = NT / 2; s > 0; s >>= 1) {
        if (t < s) sh[t] += sh[t + s];
        __syncthreads();
    }
    float r = sh[0];
    __syncthreads();
    return r;
}

template <int NT>
__device__ __forceinline__ int block_reduce_i(int v, int* sh) {
    int t = threadIdx.x;
    sh[t] = v;
    __syncthreads();
#pragma unroll
    for (int s = NT / 2; s > 0; s >>= 1) {
        if (t < s) sh[t] += sh[t + s];
        __syncthreads();
    }
    int r = sh[0];
    __syncthreads();
    return r;
}

// K1: per-row norms + packed labels. 320 blocks x 128 threads.
__global__ void __launch_bounds__(128) k_prep(const int* __restrict__ label,
                                              const float* __restrict__ src,
                                              const float* __restrict__ tgt) {
    __shared__ float sh[128];
    int i = blockIdx.x, t = threadIdx.x;

    float s = src[i * DD + t];
    float ssum = block_reduce_f<128>(s * s, sh);

    float g = tgt[i * DD + t];
    float tsum = block_reduce_f<128>(g * g, sh);

    // Labels are binary {0,1}: pack into 3 words via ballot; dot == popcount.
    bool pred = (t < CC) && (label[i * CC + t] != 0);
    unsigned bits = __ballot_sync(0xffffffffu, pred);
    int w = t >> 5;
    if ((t & 31) == 0 && w < 3) g_lp[i * 3 + w] = bits;
    float lsum = block_reduce_f<128>(pred ? 1.0f : 0.0f, sh);

    if (t == 0) {
        g_ns[i] = sqrtf(ssum);
        g_nt[i] = sqrtf(tsum);
        g_sn[i] = sqrtf(lsum);
        if (i == 0) g_done = 0;   // reset ticket every launch (stream-ordered before k_final)
    }
}

// K2: fd matrix, pos/neg mask, diversity. One block per anchor row. 320 x 128.
__global__ void __launch_bounds__(128) k_dist(const float* __restrict__ tgt) {
    __shared__ float s_src[DD];
    __shared__ unsigned s_lp[3];
    __shared__ float sh[128];
    int a = blockIdx.x, t = threadIdx.x;

    // s_src holds the SOURCE row a (read through g-norms kernel's same input via
    // constant pointer passed below) -- loaded in launch wrapper via param.
    // (filled by k_dist2-style param below)
    // NOTE: src pointer is passed via second param in the actual launch.
    // -- replaced by the real signature in kernel_launch.
    (void)tgt; (void)s_src; (void)s_lp; (void)sh; (void)a; (void)t;
}

// Real K2 (with both pointers).
__global__ void __launch_bounds__(128) k_fd(const float* __restrict__ src,
                                            const float* __restrict__ tgt) {
    __shared__ float s_src[DD];
    __shared__ unsigned s_lp[3];
    __shared__ float sh[128];
    int a = blockIdx.x, t = threadIdx.x;

    s_src[t] = src[a * DD + t];
    if (t < 3) s_lp[t] = g_lp[a * 3 + t];
    __syncthreads();

    float ns_a = g_ns[a];
    float sn_a = g_sn[a];
    unsigned la0 = s_lp[0], la1 = s_lp[1], la2 = s_lp[2];
    const float4* sp = reinterpret_cast<const float4*>(s_src);

    float divacc = 0.0f;
    for (int b = t; b < BB; b += 128) {
        const float4* tr = reinterpret_cast<const float4*>(tgt + b * DD);
        float dot = 0.0f;
#pragma unroll
        for (int k = 0; k < DD / 4; k++) {
            float4 x = sp[k];
            float4 y = tr[k];
            dot += x.x * y.x + x.y * y.y + x.z * y.z + x.w * y.w;
        }
        float denom = fmaxf(ns_a * g_nt[b], 1e-8f);
        float sim = dot / denom;
        float fdv = fmaxf(0.0f, 1.0f - sim);
        g_fd[a * BB + b] = fdv;
        divacc += fdv;

        int dl = __popc(la0 & g_lp[b * 3 + 0]) +
                 __popc(la1 & g_lp[b * 3 + 1]) +
                 __popc(la2 & g_lp[b * 3 + 2]);
        float ldv = 1.0f - fminf(1.0f, (float)dl / (sn_a * g_sn[b]));
        unsigned char m = 0;
        if (ldv >= 0.5f) m = 2;                  // negative (a,n)
        else if (ldv <= 0.2f && b != a) m = 1;   // positive (a,p), exclude diagonal
        g_mask[a * BB + b] = m;
    }

    float tot = block_reduce_f<128>(divacc, sh);
    if (t == 0) g_div[a] = tot / 320.0f;
}

// K3: anchor rank, per-anchor triplet sum, last-block deterministic finalize.
// 320 blocks x 256 threads.
__global__ void __launch_bounds__(256) k_final(float* __restrict__ out) {
    __shared__ float s_fd[BB];
    __shared__ unsigned char s_m[BB];
    __shared__ float shf[256];
    __shared__ int shi[256];
    __shared__ int s_last;
    int a = blockIdx.x, t = threadIdx.x;

    // Rank of this row's diversity (top_k semantics: larger value wins,
    // ties broken by smaller index).
    float mydiv = g_div[a];
    int cgt = 0;
    for (int j = t; j < BB; j += 256) {
        float dj = g_div[j];
        if (dj > mydiv || (dj == mydiv && j < a)) cgt++;
    }
    int rank = block_reduce_i<256>(cgt, shi);

    float lsum = 0.0f;
    int lcnt = 0;
    if (rank < NUM_ANCHORS) {
        for (int j = t; j < BB; j += 256) {
            s_fd[j] = g_fd[a * BB + j];
            s_m[j] = g_mask[a * BB + j];
        }
        __syncthreads();
        // pos/neg sets are disjoint (gamma < beta), so p != n and a != n are automatic.
        for (int idx = t; idx < BB * BB; idx += 256) {
            int p = idx / BB;
            int n = idx - p * BB;
            if (s_m[p] == 1 && s_m[n] == 2) {
                lcnt++;
                lsum += fmaxf(0.0f, s_fd[p] - s_fd[n] + 0.5f);
            }
        }
    }
    float tsum = block_reduce_f<256>(lsum, shf);
    int tcnt = block_reduce_i<256>(lcnt, shi);

    if (t == 0) {
        g_partial[a] = tsum;
        g_cnt[a] = tcnt;
        __threadfence();
        int ticket = atomicAdd(&g_done, 1);
        s_last = (ticket == BB - 1) ? 1 : 0;
    }
    __syncthreads();

    if (s_last) {
        // Deterministic fixed-order combine of all 320 partials.
        float ps = 0.0f;
        int pc = 0;
        for (int j = t; j < BB; j += 256) {
            ps += g_partial[j];
            pc += g_cnt[j];
        }
        float fs = block_reduce_f<256>(ps, shf);
        int fc = block_reduce_i<256>(pc, shi);
        if (t == 0) out[0] = fs / ((float)fc + 1e-4f);
    }
}

extern "C" void kernel_launch(void* const* d_in, const int* in_sizes, int n_in,
                              void* d_out, int out_size) {
    const int* label = (const int*)d_in[0];
    const float* src = (const float*)d_in[1];
    const float* tgt = (const float*)d_in[2];
    float* out = (float*)d_out;
    (void)in_sizes; (void)n_in; (void)out_size;

    k_prep<<<BB, 128>>>(label, src, tgt);
    k_fd<<<BB, 128>>>(src, tgt);
    k_final<<<BB, 256>>>(out);
}

// round 2
// speedup vs baseline: 1.0968x; 1.0968x over previous
#include <cuda_runtime.h>

// Problem constants (fixed by the reference).
#define BB 320          // batch
#define CC 80           // label dim
#define DD 128          // feature dim
#define NUM_ANCHORS 30
#define NB 80           // grid blocks (<=148 SMs -> co-residency guaranteed)
#define NT 256          // threads per block
#define RPB 4           // rows per block (NB * RPB == BB)

// ---------------- scratch (__device__ globals; no allocations allowed) ------
__device__ float g_ns[BB];            // ||source_i||
__device__ float g_nt[BB];            // ||target_i||
__device__ float g_sn[BB];            // sqrt(label_i . label_i)
__device__ unsigned g_lp[BB * 3];     // packed binary labels (80 bits -> 3 words)
__device__ float g_fd[BB * BB];       // cosine-distance matrix
__device__ unsigned char g_mask[BB * BB]; // 1 = positive (p!=a), 2 = negative
__device__ float g_div[BB];           // diversity = mean_b fd[a,b]
__device__ float g_bsum[NB];          // per-block loss partials
__device__ int   g_bcnt[NB];          // per-block triplet counts
__device__ unsigned g_done = 0;       // finalize ticket (self-resetting)
__device__ unsigned g_bar_cnt = 0;    // grid barrier arrival counter
__device__ volatile unsigned g_bar_gen = 0; // grid barrier generation

// ---------------- grid barrier (cg::grid_group::sync pattern) ---------------
__device__ __forceinline__ void grid_barrier() {
    __syncthreads();
    if (threadIdx.x == 0) {
        __threadfence();                       // release this block's writes
        unsigned gen = g_bar_gen;
        if (atomicAdd(&g_bar_cnt, 1u) == (unsigned)(NB - 1)) {
            atomicExch(&g_bar_cnt, 0u);
            __threadfence();
            g_bar_gen = gen + 1u;
        } else {
            while (g_bar_gen == gen) { }
            __threadfence();                   // acquire other blocks' writes
        }
    }
    __syncthreads();
}

// ---------------- deterministic block-wide sums (shuffle + fixed combine) ---
__device__ __forceinline__ float blk_sum_f(float v, volatile float* s8) {
#pragma unroll
    for (int o = 16; o > 0; o >>= 1) v += __shfl_down_sync(0xffffffffu, v, o);
    if ((threadIdx.x & 31) == 0) s8[threadIdx.x >> 5] = v;
    __syncthreads();
    float r = s8[0] + s8[1] + s8[2] + s8[3] + s8[4] + s8[5] + s8[6] + s8[7];
    __syncthreads();
    return r;
}
__device__ __forceinline__ int blk_sum_i(int v, volatile int* s8) {
#pragma unroll
    for (int o = 16; o > 0; o >>= 1) v += __shfl_down_sync(0xffffffffu, v, o);
    if ((threadIdx.x & 31) == 0) s8[threadIdx.x >> 5] = v;
    __syncthreads();
    int r = s8[0] + s8[1] + s8[2] + s8[3] + s8[4] + s8[5] + s8[6] + s8[7];
    __syncthreads();
    return r;
}

// ---------------- the one fused kernel --------------------------------------
__global__ void __launch_bounds__(NT)
triplet_fused(const int* __restrict__ label,
              const float* __restrict__ src,
              const float* __restrict__ tgt,
              float* __restrict__ out) {
    const int t = threadIdx.x;
    const int b = blockIdx.x;
    const int R0 = b * RPB;
    const int w = t >> 5;
    const int lane = t & 31;

    __shared__ float s_red[8][2];
    __shared__ unsigned char s_lab[RPB * CC];
    __shared__ float s_src[RPB][DD];
    __shared__ float s_nsa[RPB], s_sna[RPB];
    __shared__ unsigned s_la[RPB][3];
    __shared__ float s_div32[8 * RPB];
    __shared__ volatile float s_f8[8];
    __shared__ volatile int s_i8[8];
    __shared__ float s_posfd[BB];
    __shared__ int s_npos;
    __shared__ int s_rank;
    __shared__ float s_acc;
    __shared__ int s_cnt;
    __shared__ int s_last;

    // ===== Phase 0: row norms + packed labels (4 rows, 64 threads each) =====
    {
        int row = R0 + (t >> 6);
        int j = t & 63;
        const float* sp = src + row * DD;
        const float* tp = tgt + row * DD;
        float a0 = sp[j], a1 = sp[j + 64];
        float b0 = tp[j], b1 = tp[j + 64];
        float ss = a0 * a0 + a1 * a1;
        float tt = b0 * b0 + b1 * b1;
#pragma unroll
        for (int o = 16; o > 0; o >>= 1) {
            ss += __shfl_down_sync(0xffffffffu, ss, o);
            tt += __shfl_down_sync(0xffffffffu, tt, o);
        }
        if (lane == 0) { s_red[w][0] = ss; s_red[w][1] = tt; }

        // labels -> smem bytes (binary {0,1})
        for (int i = t; i < RPB * CC; i += NT) s_lab[i] = (label[R0 * CC + i] != 0);
        __syncthreads();

        if ((t & 63) == 0) {
            g_ns[row] = sqrtf(s_red[w][0] + s_red[w + 1][0]);
            g_nt[row] = sqrtf(s_red[w][1] + s_red[w + 1][1]);
        }
        if (t < RPB * 3) {
            int r = t / 3, wd = t % 3;
            int base = r * CC + wd * 32;
            int lim = (wd == 2) ? (CC - 64) : 32;
            unsigned bits = 0;
            for (int k = 0; k < lim; k++) bits |= (unsigned)s_lab[base + k] << k;
            g_lp[(R0 + r) * 3 + wd] = bits;
        }
        __syncthreads();
        if (t < RPB) {
            int r = R0 + t;
            int dl = __popc(g_lp[r * 3]) + __popc(g_lp[r * 3 + 1]) + __popc(g_lp[r * 3 + 2]);
            g_sn[r] = sqrtf((float)dl);
        }
    }

    grid_barrier();   // all norms / packed labels visible

    // ===== Phase 1: fd matrix rows, pos/neg mask, diversity =================
    {
        for (int i = t; i < RPB * DD; i += NT)
            s_src[i >> 7][i & 127] = src[R0 * DD + i];
        if (t < RPB) { s_nsa[t] = g_ns[R0 + t]; s_sna[t] = g_sn[R0 + t]; }
        if (t < RPB * 3) s_la[t / 3][t % 3] = g_lp[(R0 + t / 3) * 3 + (t % 3)];
        __syncthreads();

        float dacc0 = 0.f, dacc1 = 0.f, dacc2 = 0.f, dacc3 = 0.f;
        for (int c = t; c < BB; c += NT) {
            const float4* tr = reinterpret_cast<const float4*>(tgt + c * DD);
            float d0 = 0.f, d1 = 0.f, d2 = 0.f, d3 = 0.f;
#pragma unroll
            for (int k = 0; k < DD / 4; k++) {
                float4 y = tr[k];
                float4 x0 = reinterpret_cast<const float4*>(s_src[0])[k];
                float4 x1 = reinterpret_cast<const float4*>(s_src[1])[k];
                float4 x2 = reinterpret_cast<const float4*>(s_src[2])[k];
                float4 x3 = reinterpret_cast<const float4*>(s_src[3])[k];
                d0 += x0.x * y.x + x0.y * y.y + x0.z * y.z + x0.w * y.w;
                d1 += x1.x * y.x + x1.y * y.y + x1.z * y.z + x1.w * y.w;
                d2 += x2.x * y.x + x2.y * y.y + x2.z * y.z + x2.w * y.w;
                d3 += x3.x * y.x + x3.y * y.y + x3.z * y.z + x3.w * y.w;
            }
            float ntc = g_nt[c];
            float snc = g_sn[c];
            unsigned lb0 = g_lp[c * 3], lb1 = g_lp[c * 3 + 1], lb2 = g_lp[c * 3 + 2];
            float dd[4] = {d0, d1, d2, d3};
#pragma unroll
            for (int r = 0; r < RPB; r++) {
                float denom = fmaxf(s_nsa[r] * ntc, 1e-8f);
                float fdv = fmaxf(0.f, 1.f - dd[r] / denom);
                g_fd[(R0 + r) * BB + c] = fdv;
                if (r == 0) dacc0 += fdv;
                else if (r == 1) dacc1 += fdv;
                else if (r == 2) dacc2 += fdv;
                else dacc3 += fdv;
                int dl = __popc(s_la[r][0] & lb0) + __popc(s_la[r][1] & lb1) +
                         __popc(s_la[r][2] & lb2);
                float ldv = 1.f - fminf(1.f, (float)dl / (s_sna[r] * snc));
                unsigned char m = 0;
                if (ldv >= 0.5f) m = 2;                          // negative
                else if (ldv <= 0.2f && c != (R0 + r)) m = 1;    // positive
                g_mask[(R0 + r) * BB + c] = m;
            }
        }
#pragma unroll
        for (int o = 16; o > 0; o >>= 1) {
            dacc0 += __shfl_down_sync(0xffffffffu, dacc0, o);
            dacc1 += __shfl_down_sync(0xffffffffu, dacc1, o);
            dacc2 += __shfl_down_sync(0xffffffffu, dacc2, o);
            dacc3 += __shfl_down_sync(0xffffffffu, dacc3, o);
        }
        if (lane == 0) {
            s_div32[w * RPB + 0] = dacc0;
            s_div32[w * RPB + 1] = dacc1;
            s_div32[w * RPB + 2] = dacc2;
            s_div32[w * RPB + 3] = dacc3;
        }
        __syncthreads();
        if (t < RPB) {
            float s = 0.f;
#pragma unroll
            for (int ww = 0; ww < 8; ww++) s += s_div32[ww * RPB + t];
            g_div[R0 + t] = s / 320.f;
        }
    }

    grid_barrier();   // all g_div visible (fd/mask for own rows are block-local)

    // ===== Phase 2: rank own rows, compact positives, pair-sum anchors ======
    if (t == 0) { s_acc = 0.f; s_cnt = 0; }
    __syncthreads();

    for (int r = 0; r < RPB; r++) {
        const int a = R0 + r;
        // rank among g_div with top_k tie-break (larger value, lower index wins)
        float da = g_div[a];
        int cgt = 0;
        for (int j = t; j < BB; j += NT) {
            float dj = g_div[j];
            cgt += (dj > da || (dj == da && j < a)) ? 1 : 0;
        }
        int rank = blk_sum_i(cgt, s_i8);
        if (t == 0) s_rank = rank;
        __syncthreads();

        if (s_rank < NUM_ANCHORS) {
            // deterministic positive-list compaction by warp 0
            if (t < 32) {
                int np = 0;
                for (int j0 = 0; j0 < BB; j0 += 32) {
                    int j = j0 + t;
                    bool p = (g_mask[a * BB + j] == 1);
                    unsigned bal = __ballot_sync(0xffffffffu, p);
                    if (p) s_posfd[np + __popc(bal & ((1u << t) - 1u))] = g_fd[a * BB + j];
                    np += __popc(bal);
                }
                if (t == 0) s_npos = np;
            }
            __syncthreads();
            int np = s_npos;

            float rsum = 0.f;
            int rnn = 0;
            if (np > 0) {
                for (int j = t; j < BB; j += NT) {
                    if (g_mask[a * BB + j] == 2) {
                        rnn++;
                        float fn = g_fd[a * BB + j];
                        for (int p = 0; p < np; p++)
                            rsum += fmaxf(0.f, (s_posfd[p] - fn) + 0.5f);
                    }
                }
            } else {
                for (int j = t; j < BB; j += NT)
                    rnn += (g_mask[a * BB + j] == 2) ? 1 : 0;
            }
            float tsum = blk_sum_f(rsum, s_f8);
            int tnn = blk_sum_i(rnn, s_i8);
            if (t == 0) { s_acc += tsum; s_cnt += np * tnn; }
            __syncthreads();
        }
    }

    // ===== finalize: last-block ticket, fixed-order combine ================
    if (t == 0) {
        g_bsum[b] = s_acc;
        g_bcnt[b] = s_cnt;
        __threadfence();
        unsigned tk = atomicAdd(&g_done, 1u);
        s_last = (tk == (unsigned)(NB - 1)) ? 1 : 0;
    }
    __syncthreads();

    if (s_last) {
        if (t == 0) g_done = 0;        // reset for next graph replay
        __threadfence();               // acquire all blocks' partials
        float ps = (t < NB) ? g_bsum[t] : 0.f;
        int pc = (t < NB) ? g_bcnt[t] : 0;
        float fs = blk_sum_f(ps, s_f8);
        int fc = blk_sum_i(pc, s_i8);
        if (t == 0) out[0] = fs / ((float)fc + 1e-4f);
    }
}

extern "C" void kernel_launch(void* const* d_in, const int* in_sizes, int n_in,
                              void* d_out, int out_size) {
    const int* label = (const int*)d_in[0];
    const float* src = (const float*)d_in[1];
    const float* tgt = (const float*)d_in[2];
    float* out = (float*)d_out;
    (void)in_sizes; (void)n_in; (void)out_size;

    triplet_fused<<<NB, NT>>>(label, src, tgt, out);
}